// round 1
// baseline (speedup 1.0000x reference)
#include <cuda_runtime.h>
#include <cuda_bf16.h>

// Fused Swin window-attention (quadratic normalization), fp32 baseline.
// One CTA per window (B=4096). All intermediates live in SMEM:
//   x[49x384] -> per-head qkv[49x96] -> attn[49x49] -> head outs -> proj.
// Weights streamed global->SMEM in K=32 chunks (L2-resident across CTAs).

#define NW    49
#define DIMC  384
#define NH    12
#define HD    32
#define SCALE 0.17677669529663687f   // 32^-0.5

// SMEM layout (floats)
#define OFF_XW    0          // 18816: x during attention phases, w_proj chunks during proj
#define OFF_OUT   18816      // 18816: concatenated head outputs [49][384]
#define OFF_QKV   37632      // 49*97 (pad->4756): per-head q|k|v, row stride 97 (odd, conflict-free)
#define OFF_ATTN  42388      // 2401 (pad->2404)
#define OFF_RSUM  44792      // 49 (pad->56): reciprocal row sums
#define OFF_W     44848      // 32*96 = 3072: qkv weight chunk
#define OFF_BIAS  47920      // 169*12 = 2028: bias_table
#define OFF_REL   49948      // 2401 ints: rel_pos_index
#define SMEM_FLOATS 52349
#define SMEM_BYTES  (SMEM_FLOATS * 4)

#define QKV_STRIDE 97

__global__ void __launch_bounds__(256, 1)
win_attn_kernel(const float* __restrict__ x,
                const float* __restrict__ w_qkv,
                const float* __restrict__ w_proj,
                const float* __restrict__ b_proj,
                const float* __restrict__ bias_table,
                const int*   __restrict__ rel_idx,
                float*       __restrict__ out)
{
    extern __shared__ __align__(16) float smem[];
    float* sXW   = smem + OFF_XW;
    float* sOut  = smem + OFF_OUT;
    float* sQKV  = smem + OFF_QKV;
    float* sAttn = smem + OFF_ATTN;
    float* sRsum = smem + OFF_RSUM;
    float* sW    = smem + OFF_W;
    float* sBias = smem + OFF_BIAS;
    int*   sRel  = (int*)(smem + OFF_REL);

    const int tid  = threadIdx.x;
    const int warp = tid >> 5;
    const int lane = tid & 31;
    const int b    = blockIdx.x;

    // ---- Phase 0: stage x, bias table, rel index -------------------------
    {
        const float4* xg = (const float4*)(x + (size_t)b * NW * DIMC);
        #pragma unroll
        for (int i = 0; i < 19; ++i) {          // 4704 float4 / 256 = 18.375
            int idx = tid + i * 256;
            if (idx < NW * DIMC / 4) ((float4*)sXW)[idx] = xg[idx];
        }
        for (int i = tid; i < 169 * NH; i += 256) sBias[i] = bias_table[i];
        for (int i = tid; i < NW * NW; i += 256)  sRel[i]  = rel_idx[i];
    }
    __syncthreads();

    // rows handled by this thread: r = warp + 8*j  (warp0 -> 7 rows, else 6)
    // ---- Phase 1: per-head QKV + attention -------------------------------
    for (int h = 0; h < NH; ++h) {
        // --- QKV GEMM: [49x384] @ [384x96] -> sQKV (q scaled) ---
        float acc[7][3];
        #pragma unroll
        for (int j = 0; j < 7; ++j) { acc[j][0] = 0.f; acc[j][1] = 0.f; acc[j][2] = 0.f; }

        for (int kb = 0; kb < DIMC; kb += 32) {
            // load weight chunk [32][96]: cols = (q|k|v) of head h
            #pragma unroll
            for (int i = 0; i < 3; ++i) {
                int idx = tid + i * 256;            // < 768
                int kk  = idx / 24;
                int rem = idx % 24;
                int seg = rem >> 3;                 // 0=q 1=k 2=v
                int m   = rem & 7;
                float4 wv = *(const float4*)(w_qkv + (size_t)(kb + kk) * (3 * DIMC)
                                             + seg * DIMC + h * HD + m * 4);
                *(float4*)(sW + kk * 96 + seg * 32 + m * 4) = wv;
            }
            __syncthreads();
            #pragma unroll 8
            for (int kk = 0; kk < 32; ++kk) {
                float w0 = sW[kk * 96 + lane];
                float w1 = sW[kk * 96 + lane + 32];
                float w2 = sW[kk * 96 + lane + 64];
                #pragma unroll
                for (int j = 0; j < 7; ++j) {
                    // rows >=49 compute garbage but stay in-bounds; stores guarded
                    float xv = sXW[(warp + 8 * j) * DIMC + kb + kk];
                    acc[j][0] = fmaf(xv, w0, acc[j][0]);
                    acc[j][1] = fmaf(xv, w1, acc[j][1]);
                    acc[j][2] = fmaf(xv, w2, acc[j][2]);
                }
            }
            __syncthreads();
        }
        #pragma unroll
        for (int j = 0; j < 7; ++j) {
            int r = warp + 8 * j;
            if (r < NW) {
                sQKV[r * QKV_STRIDE + lane]      = acc[j][0] * SCALE;  // q pre-scaled
                sQKV[r * QKV_STRIDE + lane + 32] = acc[j][1];          // k
                sQKV[r * QKV_STRIDE + lane + 64] = acc[j][2];          // v
            }
        }
        __syncthreads();

        // --- scores: attn[r][c] = (q.k + bias)^2 ---
        for (int idx = tid; idx < NW * NW; idx += 256) {
            int r = idx / NW, c = idx - r * NW;
            const float* qr = sQKV + r * QKV_STRIDE;
            const float* kc = sQKV + c * QKV_STRIDE + 32;
            float s = 0.f;
            #pragma unroll
            for (int d = 0; d < HD; ++d) s = fmaf(qr[d], kc[d], s);
            s += sBias[sRel[idx] * NH + h];
            sAttn[idx] = s * s;
        }
        __syncthreads();

        // --- row sums -> reciprocal ---
        for (int r = warp; r < NW; r += 8) {
            float s = sAttn[r * NW + lane];
            if (lane + 32 < NW) s += sAttn[r * NW + lane + 32];
            #pragma unroll
            for (int o = 16; o > 0; o >>= 1) s += __shfl_xor_sync(0xFFFFFFFFu, s, o);
            if (lane == 0) sRsum[r] = 1.0f / (s + 1e-6f);
        }
        __syncthreads();

        // --- out_h = (attn/rowsum) @ v, write into sOut columns h*32.. ---
        for (int idx = tid; idx < NW * HD; idx += 256) {
            int r = idx >> 5, d = idx & 31;
            const float* ar = sAttn + r * NW;
            float a = 0.f;
            #pragma unroll
            for (int c = 0; c < NW; ++c) a = fmaf(ar[c], sQKV[c * QKV_STRIDE + 64 + d], a);
            sOut[r * DIMC + h * HD + d] = a * sRsum[r];
        }
        __syncthreads();
    }

    // ---- Phase 2: projection  out = sOut @ w_proj + b_proj ---------------
    float bpr[12];
    #pragma unroll
    for (int m = 0; m < 12; ++m) bpr[m] = b_proj[lane + 32 * m];

    float pacc[7][12];
    #pragma unroll
    for (int j = 0; j < 7; ++j)
        #pragma unroll
        for (int m = 0; m < 12; ++m) pacc[j][m] = 0.f;

    for (int kb = 0; kb < DIMC; kb += 32) {
        // load w_proj chunk [32][384] into sXW (x no longer needed)
        #pragma unroll
        for (int i = 0; i < 12; ++i) {
            int idx = tid + i * 256;              // < 3072
            int kk  = idx / 96;
            int m   = idx - kk * 96;
            *(float4*)(sXW + kk * DIMC + m * 4) =
                *(const float4*)(w_proj + (size_t)(kb + kk) * DIMC + m * 4);
        }
        __syncthreads();
        #pragma unroll 4
        for (int kk = 0; kk < 32; ++kk) {
            float wv[12];
            #pragma unroll
            for (int m = 0; m < 12; ++m) wv[m] = sXW[kk * DIMC + lane + 32 * m];
            #pragma unroll
            for (int j = 0; j < 7; ++j) {
                float xv = sOut[(warp + 8 * j) * DIMC + kb + kk];  // in-bounds garbage for r>=49
                #pragma unroll
                for (int m = 0; m < 12; ++m) pacc[j][m] = fmaf(xv, wv[m], pacc[j][m]);
            }
        }
        __syncthreads();
    }

    float* og = out + (size_t)b * NW * DIMC;
    #pragma unroll
    for (int j = 0; j < 7; ++j) {
        int r = warp + 8 * j;
        if (r < NW) {
            #pragma unroll
            for (int m = 0; m < 12; ++m)
                og[r * DIMC + lane + 32 * m] = pacc[j][m] + bpr[m];
        }
    }
}

extern "C" void kernel_launch(void* const* d_in, const int* in_sizes, int n_in,
                              void* d_out, int out_size) {
    const float* x          = (const float*)d_in[0];
    const float* w_qkv      = (const float*)d_in[1];
    const float* w_proj     = (const float*)d_in[2];
    const float* b_proj     = (const float*)d_in[3];
    const float* bias_table = (const float*)d_in[4];
    const int*   rel_idx    = (const int*)d_in[5];
    float* out = (float*)d_out;

    int B = in_sizes[0] / (NW * DIMC);   // 4096

    cudaFuncSetAttribute(win_attn_kernel,
                         cudaFuncAttributeMaxDynamicSharedMemorySize, SMEM_BYTES);
    win_attn_kernel<<<B, 256, SMEM_BYTES>>>(x, w_qkv, w_proj, b_proj,
                                            bias_table, rel_idx, out);
}